// round 13
// baseline (speedup 1.0000x reference)
#include <cuda_runtime.h>
#include <math.h>
#include <stdint.h>

#define NN   20000
#define DIN  1024
#define DOU  64
#define NE   320000
#define SZ   (NN*DOU)

// Output layout (flattened tuple, float32):
//   hiden_emb [N,64], h [N,1024], ret [N,1], ret_a [N,1], mean [N,1024], disp [N,1024]
#define OFF_HIDEN 0
#define OFF_H     ((size_t)SZ)
#define OFF_RET   (OFF_H + (size_t)NN*DIN)
#define OFF_RETA  (OFF_RET + NN)
#define OFF_MEAN  (OFF_RETA + NN)
#define OFF_DISP  (OFF_MEAN + (size_t)NN*DIN)

// Scratch
__device__ float g_z0[SZ];
__device__ float g_za0[SZ];
__device__ float g_zaacc[SZ];
__device__ float g_zsacc[SZ];
__device__ float g_t[SZ];

// ---------------------------------------------------------------------------
// helpers
// ---------------------------------------------------------------------------
__device__ __forceinline__ void red4(float* p, float a, float b, float c, float d) {
    asm volatile("red.global.add.v4.f32 [%0], {%1,%2,%3,%4};"
                 :: "l"(p), "f"(a), "f"(b), "f"(c), "f"(d) : "memory");
}

// round-to-nearest tf32 (returned as fp32 bit pattern)
__device__ __forceinline__ float tf32r(float x) {
    uint32_t u;
    asm("cvt.rna.tf32.f32 %0, %1;" : "=r"(u) : "f"(x));
    return __uint_as_float(u);
}
__device__ __forceinline__ float4 tf32r4(float4 v) {
    return make_float4(tf32r(v.x), tf32r(v.y), tf32r(v.z), tf32r(v.w));
}

// m16n8k8 tf32 MMA (row.col), D += A*B
__device__ __forceinline__ void mma_tf32(float* d, uint32_t a0, uint32_t a1,
                                         uint32_t a2, uint32_t a3,
                                         uint32_t b0, uint32_t b1) {
    asm("mma.sync.aligned.m16n8k8.row.col.f32.tf32.tf32.f32 "
        "{%0,%1,%2,%3}, {%4,%5,%6,%7}, {%8,%9}, {%0,%1,%2,%3};"
        : "+f"(d[0]), "+f"(d[1]), "+f"(d[2]), "+f"(d[3])
        : "r"(a0), "r"(a1), "r"(a2), "r"(a3), "r"(b0), "r"(b1));
}

#define XPAD 68   // row stride of X smem tiles [64 rows][64 k]
#define WPAD 72   // row stride of W smem tiles [64 k][64 n] (phase1)

// Warp computes a 32x32 output tile over a 64-deep k reduction (phase1).
__device__ __forceinline__ void warp_mma_64k(const float* __restrict__ Xs,
                                             const float* __restrict__ Ws,
                                             int ro, int co, int lane,
                                             float acc[2][4][4]) {
    int gid = lane >> 2, tig = lane & 3;
#pragma unroll
    for (int kk = 0; kk < 64; kk += 8) {
        uint32_t a[2][4];
#pragma unroll
        for (int mi = 0; mi < 2; mi++) {
            const float* base = Xs + (ro + mi * 16 + gid) * XPAD + kk + tig;
            a[mi][0] = __float_as_uint(base[0]);
            a[mi][1] = __float_as_uint(base[8 * XPAD]);
            a[mi][2] = __float_as_uint(base[4]);
            a[mi][3] = __float_as_uint(base[8 * XPAD + 4]);
        }
#pragma unroll
        for (int ni = 0; ni < 4; ni++) {
            const float* wb = Ws + (kk + tig) * WPAD + co + ni * 8 + gid;
            uint32_t b0 = __float_as_uint(wb[0]);
            uint32_t b1 = __float_as_uint(wb[4 * WPAD]);
#pragma unroll
            for (int mi = 0; mi < 2; mi++)
                mma_tf32(acc[mi][ni], a[mi][0], a[mi][1], a[mi][2], a[mi][3],
                         b0, b1);
        }
    }
}

// ---------------------------------------------------------------------------
// Input GEMM (tf32): C[64-row tile, 64] = A[.,1024] @ B[1024,64]
// ---------------------------------------------------------------------------
__device__ __forceinline__ void gemm_in_tf32(const float* __restrict__ A,
                                             const float* __restrict__ B,
                                             float* __restrict__ C, int bx) {
    __shared__ float As[64 * XPAD];
    __shared__ float Bs[64 * WPAD];

    int tid = threadIdx.x;
    int w = tid >> 5, lane = tid & 31;
    int wr = w & 1, wc = w >> 1;
    int rb = bx * 64;

    float acc[2][4][4];
#pragma unroll
    for (int mi = 0; mi < 2; mi++)
#pragma unroll
        for (int ni = 0; ni < 4; ni++)
#pragma unroll
            for (int q = 0; q < 4; q++) acc[mi][ni][q] = 0.f;

    for (int k0 = 0; k0 < DIN; k0 += 64) {
#pragma unroll
        for (int i = 0; i < 8; i++) {
            int chunk = tid + 128 * i;
            int r = chunk >> 4, k4 = (chunk & 15) << 2;
            int gr = rb + r;
            float4 v = (gr < NN)
                ? __ldg((const float4*)&A[(size_t)gr * DIN + k0 + k4])
                : make_float4(0.f, 0.f, 0.f, 0.f);
            *(float4*)&As[r * XPAD + k4] = tf32r4(v);
        }
#pragma unroll
        for (int i = 0; i < 8; i++) {
            int chunk = tid + 128 * i;
            int k = chunk >> 4, n4 = (chunk & 15) << 2;
            float4 v = __ldg((const float4*)&B[(size_t)(k0 + k) * DOU + n4]);
            *(float4*)&Bs[k * WPAD + n4] = tf32r4(v);
        }
        __syncthreads();
        warp_mma_64k(As, Bs, wr * 32, wc * 32, lane, acc);
        __syncthreads();
    }

    int gid = lane >> 2, tig = lane & 3;
#pragma unroll
    for (int mi = 0; mi < 2; mi++) {
#pragma unroll
        for (int ni = 0; ni < 4; ni++) {
            int r0 = rb + wr * 32 + mi * 16 + gid;
            int c  = wc * 32 + ni * 8 + tig * 2;
            if (r0 < NN)
                *(float2*)&C[(size_t)r0 * DOU + c] =
                    make_float2(acc[mi][ni][0], acc[mi][ni][1]);
            if (r0 + 8 < NN)
                *(float2*)&C[(size_t)(r0 + 8) * DOU + c] =
                    make_float2(acc[mi][ni][2], acc[mi][ni][3]);
        }
    }
}

#define GEMM_BLKS 313   // ceil(20000/64)
#define ZERO_BLKS 256

// Phase 1: z0 = feat@W1 ; za0 = feat_a@W1 ; zero the 4 accumulators
__global__ __launch_bounds__(128) void k_phase1(
        const float* __restrict__ feat, const float* __restrict__ feat_a,
        const float* __restrict__ W1,
        float* __restrict__ z0, float* __restrict__ za0,
        float4* __restrict__ zout, float4* __restrict__ zaacc,
        float4* __restrict__ zsacc, float4* __restrict__ t) {
    int b = blockIdx.x;
    if (b < GEMM_BLKS) {
        gemm_in_tf32(feat, W1, z0, b);
    } else if (b < 2 * GEMM_BLKS) {
        gemm_in_tf32(feat_a, W1, za0, b - GEMM_BLKS);
    } else {
        int i = (b - 2 * GEMM_BLKS) * 128 + threadIdx.x;
        int stride = ZERO_BLKS * 128;
        float4 zv = make_float4(0.f, 0.f, 0.f, 0.f);
        for (int j = i; j < SZ / 4; j += stride) {
            zout[j] = zv; zaacc[j] = zv; zsacc[j] = zv; t[j] = zv;
        }
    }
}

// ---------------------------------------------------------------------------
// SpMM bodies (16 threads/edge, red.global.add.v4)
// ---------------------------------------------------------------------------
__device__ __forceinline__ void spmm_dual_body(unsigned idx,
        const int* __restrict__ row, const int* __restrict__ col,
        const float* __restrict__ vals,
        const float* __restrict__ x1, float* y1,
        const float* __restrict__ x2, float* y2) {
    unsigned e = idx >> 4;
    if (e >= NE) return;
    int lane4 = (idx & 15) << 2;
    int r = __ldg(&row[e]), c = __ldg(&col[e]);
    float v = __ldg(&vals[e]);

    const float4 a = __ldg((const float4*)&x1[(size_t)c * DOU + lane4]);
    red4(&y1[(size_t)r * DOU + lane4], v * a.x, v * a.y, v * a.z, v * a.w);

    const float4 bb = __ldg((const float4*)&x2[(size_t)c * DOU + lane4]);
    red4(&y2[(size_t)r * DOU + lane4], v * bb.x, v * bb.y, v * bb.z, v * bb.w);
}

__device__ __forceinline__ void spmm_single_body(unsigned idx,
        const int* __restrict__ row, const int* __restrict__ col,
        const float* __restrict__ vals,
        const float* __restrict__ x1, float* y1) {
    unsigned e = idx >> 4;
    if (e >= NE) return;
    int lane4 = (idx & 15) << 2;
    int r = __ldg(&row[e]), c = __ldg(&col[e]);
    float v = __ldg(&vals[e]);

    const float4 a = __ldg((const float4*)&x1[(size_t)c * DOU + lane4]);
    red4(&y1[(size_t)r * DOU + lane4], v * a.x, v * a.y, v * a.z, v * a.w);
}

#define SP_BLKS 20000   // NE*16/256

// Phase 2: z = A z0, zaacc = A za0  ||  zsacc = A_a za0
__global__ __launch_bounds__(256) void k_phase2(
        const int* __restrict__ row,  const int* __restrict__ col,
        const float* __restrict__ vals,
        const int* __restrict__ row_a, const int* __restrict__ col_a,
        const float* __restrict__ vals_a,
        const float* __restrict__ z0, const float* __restrict__ za0,
        float* __restrict__ zout, float* __restrict__ zaacc,
        float* __restrict__ zsacc) {
    int b = blockIdx.x;
    if (b < SP_BLKS) {
        unsigned idx = (unsigned)b * 256u + threadIdx.x;
        spmm_dual_body(idx, row, col, vals, z0, zout, za0, zaacc);
    } else {
        unsigned idx = (unsigned)(b - SP_BLKS) * 256u + threadIdx.x;
        spmm_single_body(idx, row_a, col_a, vals_a, za0, zsacc);
    }
}

#define BI_BLKS 2500   // NN/8

// Phase 3: t = A z  ||  bilinear discriminators
__global__ __launch_bounds__(256) void k_phase3(
        const int* __restrict__ row, const int* __restrict__ col,
        const float* __restrict__ vals,
        const float* __restrict__ z, float* __restrict__ t,
        const float* __restrict__ za, const float* __restrict__ zsv,
        const float* __restrict__ W, const float* __restrict__ bptr,
        float* __restrict__ ret, float* __restrict__ reta) {
    int b = blockIdx.x;
    if (b < SP_BLKS) {
        unsigned idx = (unsigned)b * 256u + threadIdx.x;
        spmm_single_body(idx, row, col, vals, z, t);
    } else {
        __shared__ float Ws[64 * 65];
        __shared__ float ce[8][64], ca[8][64], cs[8][64];

        int tid = threadIdx.x;
        for (int idx = tid; idx < 4096; idx += 256) {
            int d = idx >> 6, k = idx & 63;
            Ws[d * 65 + k] = W[idx];
        }

        int w = tid >> 5, lane = tid & 31;
        int rowb = (b - SP_BLKS) * 8 + w;

#pragma unroll
        for (int jj = 0; jj < 2; jj++) {
            int j = lane + jj * 32;
            ce[w][j] = fmaxf(z  [(size_t)rowb * DOU + j], 0.f);
            ca[w][j] = fmaxf(za [(size_t)rowb * DOU + j], 0.f);
            cs[w][j] = fmaxf(zsv[(size_t)rowb * DOU + j], 0.f);
        }
        __syncthreads();

        float r1 = 0.f, r2 = 0.f;
#pragma unroll
        for (int dd = 0; dd < 2; dd++) {
            int d = lane + dd * 32;
            float s1 = 0.f, s2 = 0.f;
#pragma unroll
            for (int k = 0; k < 64; k++) {
                float wv = Ws[d * 65 + k];
                s1 = fmaf(wv, ce[w][k], s1);
                s2 = fmaf(wv, ca[w][k], s2);
            }
            r1 = fmaf(ca[w][d], s1, r1);
            r2 = fmaf(cs[w][d], s2, r2);
        }
#pragma unroll
        for (int off = 16; off; off >>= 1) {
            r1 += __shfl_down_sync(0xffffffffu, r1, off);
            r2 += __shfl_down_sync(0xffffffffu, r2, off);
        }
        if (lane == 0) {
            float bv = bptr[0];
            ret[rowb]  = r1 + bv;
            reta[rowb] = r2 + bv;
        }
    }
}

// ---------------------------------------------------------------------------
// Phase 4 (tf32 tensor): block computes rows[rb,rb+64) x cols[cb,cb+128) of
// BOTH h = T@W2 and zinb = Z0@W2 (-> mean/disp), sharing one W2 smem tile.
// 8 warps: mat(2) x wc(4); each warp owns a 64x32 tile (4 m-frags x 4 n-frags)
// => 25% fewer fragment bytes per output than 32x32 warp tiles.
// Epilogue stages through smem so gmem stores are full 128B lines.
// ---------------------------------------------------------------------------
#define WP2 136   // W2 tile row stride (128 cols + 8) ; 136 % 32 == 8 (bank-clean)
#define SP2 132   // staging tile row stride (128 cols + 4)
#define WIDE_SMEM ((2 * 64 * XPAD + 64 * WP2) * 4)   // 34816 + 34816 = 69632 B

__global__ __launch_bounds__(256) void k_wide(
        const float* __restrict__ T, const float* __restrict__ Z0,
        const float* __restrict__ W2,
        float* __restrict__ hout, float* __restrict__ meanout,
        float* __restrict__ dispout) {
    extern __shared__ float sm[];
    float* Ts = sm;                    // [64][XPAD]
    float* Zs = sm + 64 * XPAD;        // [64][XPAD]
    float* Ws = sm + 2 * 64 * XPAD;    // [64 k][WP2] (128 cols)

    int tid = threadIdx.x;
    int colTile = blockIdx.x & 7;      // 8 x 128 = 1024 cols
    int rowTile = blockIdx.x >> 3;     // 313 x 64 rows
    int rb = rowTile * 64;
    int cb = colTile * 128;

    // stage T/Z tiles [64 rows][64 k]
#pragma unroll
    for (int i = 0; i < 4; i++) {
        int chunk = tid + 256 * i;     // 1024 float4 chunks
        int r = chunk >> 4, k4 = (chunk & 15) << 2;
        int gr = rb + r;
        float4 tv = make_float4(0.f, 0.f, 0.f, 0.f), zv = tv;
        if (gr < NN) {
            tv = __ldg((const float4*)&T [(size_t)gr * DOU + k4]);
            zv = __ldg((const float4*)&Z0[(size_t)gr * DOU + k4]);
        }
        *(float4*)&Ts[r * XPAD + k4] = tf32r4(tv);
        *(float4*)&Zs[r * XPAD + k4] = tf32r4(zv);
    }
    // stage W2 tile [64 k][128 n]
#pragma unroll
    for (int i = 0; i < 8; i++) {
        int chunk = tid + 256 * i;     // 2048 float4 chunks
        int k = chunk >> 5, n4 = (chunk & 31) << 2;
        float4 v = __ldg((const float4*)&W2[(size_t)k * DIN + cb + n4]);
        *(float4*)&Ws[k * WP2 + n4] = tf32r4(v);
    }
    __syncthreads();

    int w = tid >> 5, lane = tid & 31;
    int mat = w & 1, wc = w >> 1;      // wc in 0..3
    const float* Xs = mat ? Zs : Ts;
    int gid = lane >> 2, tig = lane & 3;
    int co = wc * 32;

    float acc[4][4][4];                // [mi][ni][quad]
#pragma unroll
    for (int mi = 0; mi < 4; mi++)
#pragma unroll
        for (int ni = 0; ni < 4; ni++)
#pragma unroll
            for (int q = 0; q < 4; q++) acc[mi][ni][q] = 0.f;

#pragma unroll
    for (int kk = 0; kk < 64; kk += 8) {
        uint32_t a[4][4];
#pragma unroll
        for (int mi = 0; mi < 4; mi++) {
            const float* base = Xs + (mi * 16 + gid) * XPAD + kk + tig;
            a[mi][0] = __float_as_uint(base[0]);
            a[mi][1] = __float_as_uint(base[8 * XPAD]);
            a[mi][2] = __float_as_uint(base[4]);
            a[mi][3] = __float_as_uint(base[8 * XPAD + 4]);
        }
#pragma unroll
        for (int ni = 0; ni < 4; ni++) {
            const float* wb = Ws + (kk + tig) * WP2 + co + ni * 8 + gid;
            uint32_t b0 = __float_as_uint(wb[0]);
            uint32_t b1 = __float_as_uint(wb[4 * WP2]);
#pragma unroll
            for (int mi = 0; mi < 4; mi++)
                mma_tf32(acc[mi][ni], a[mi][0], a[mi][1], a[mi][2], a[mi][3],
                         b0, b1);
        }
    }
    __syncthreads();   // done reading Ts/Zs/Ws

    // Reuse smem start as a [64][SP2] staging tile (33792 B < Ts+Zs region)
    float* S = sm;

    // ---- h: mat0 warps deposit, all threads stream out full rows ----
    if (mat == 0) {
#pragma unroll
        for (int mi = 0; mi < 4; mi++)
#pragma unroll
            for (int ni = 0; ni < 4; ni++) {
                int r = mi * 16 + gid;
                int c = co + ni * 8 + tig * 2;
                *(float2*)&S[r * SP2 + c] =
                    make_float2(acc[mi][ni][0], acc[mi][ni][1]);
                *(float2*)&S[(r + 8) * SP2 + c] =
                    make_float2(acc[mi][ni][2], acc[mi][ni][3]);
            }
    }
    __syncthreads();
#pragma unroll
    for (int i = 0; i < 8; i++) {
        int chunk = tid + 256 * i;     // 2048 chunks: 64 rows x 32 float4
        int r = chunk >> 5, c4 = (chunk & 31) << 2;
        int gr = rb + r;
        if (gr < NN)
            __stcs((float4*)&hout[(size_t)gr * DIN + cb + c4],
                   *(const float4*)&S[r * SP2 + c4]);
    }
    __syncthreads();

    // ---- zinb: mat1 warps deposit, all threads compute mean/disp out ----
    if (mat == 1) {
#pragma unroll
        for (int mi = 0; mi < 4; mi++)
#pragma unroll
            for (int ni = 0; ni < 4; ni++) {
                int r = mi * 16 + gid;
                int c = co + ni * 8 + tig * 2;
                *(float2*)&S[r * SP2 + c] =
                    make_float2(acc[mi][ni][0], acc[mi][ni][1]);
                *(float2*)&S[(r + 8) * SP2 + c] =
                    make_float2(acc[mi][ni][2], acc[mi][ni][3]);
            }
    }
    __syncthreads();
#pragma unroll
    for (int i = 0; i < 8; i++) {
        int chunk = tid + 256 * i;
        int r = chunk >> 5, c4 = (chunk & 31) << 2;
        int gr = rb + r;
        if (gr < NN) {
            float4 x = *(const float4*)&S[r * SP2 + c4];
            size_t o = (size_t)gr * DIN + cb + c4;
            float4 mv, dv;
            float* xp = &x.x; float* mp = &mv.x; float* dp = &dv.x;
#pragma unroll
            for (int c = 0; c < 4; c++) {
                mp[c] = fminf(fmaxf(__expf(xp[c]), 1e-5f), 1e6f);
                float sp = fmaxf(xp[c], 0.f) + __logf(1.f + __expf(-fabsf(xp[c])));
                dp[c] = fminf(fmaxf(sp, 1e-4f), 1e4f);
            }
            __stcs((float4*)&meanout[o], mv);
            __stcs((float4*)&dispout[o], dv);
        }
    }
}

// ---------------------------------------------------------------------------
extern "C" void kernel_launch(void* const* d_in, const int* in_sizes, int n_in,
                              void* d_out, int out_size) {
    const float* feat   = (const float*)d_in[0];
    const float* feat_a = (const float*)d_in[1];
    const int*   row    = (const int*)  d_in[2];
    const int*   col    = (const int*)  d_in[3];
    const float* vals   = (const float*)d_in[4];
    const int*   row_a  = (const int*)  d_in[5];
    const int*   col_a  = (const int*)  d_in[6];
    const float* vals_a = (const float*)d_in[7];
    const float* W1     = (const float*)d_in[8];
    const float* W2     = (const float*)d_in[9];
    const float* discW  = (const float*)d_in[10];
    const float* discB  = (const float*)d_in[11];

    float* out = (float*)d_out;
    float* z_out    = out + OFF_HIDEN;
    float* h_out    = out + OFF_H;
    float* ret_out  = out + OFF_RET;
    float* reta_out = out + OFF_RETA;
    float* mean_out = out + OFF_MEAN;
    float* disp_out = out + OFF_DISP;

    float *p_z0, *p_za0, *p_zaacc, *p_zsacc, *p_t;
    cudaGetSymbolAddress((void**)&p_z0,    g_z0);
    cudaGetSymbolAddress((void**)&p_za0,   g_za0);
    cudaGetSymbolAddress((void**)&p_zaacc, g_zaacc);
    cudaGetSymbolAddress((void**)&p_zsacc, g_zsacc);
    cudaGetSymbolAddress((void**)&p_t,     g_t);

    static int smem_set = 0;
    if (!smem_set) {
        cudaFuncSetAttribute(k_wide, cudaFuncAttributeMaxDynamicSharedMemorySize,
                             WIDE_SMEM);
        smem_set = 1;
    }

    // 1. z0/za0 GEMMs (tf32 tensor) + zero accumulators
    k_phase1<<<2 * GEMM_BLKS + ZERO_BLKS, 128>>>(
        feat, feat_a, W1, p_z0, p_za0,
        (float4*)z_out, (float4*)p_zaacc, (float4*)p_zsacc, (float4*)p_t);

    // 2. spmm_dual(A: z0->z, za0->zaacc) || spmm(A_a: za0->zsacc)
    k_phase2<<<2 * SP_BLKS, 256>>>(
        row, col, vals, row_a, col_a, vals_a,
        p_z0, p_za0, z_out, p_zaacc, p_zsacc);

    // 3. t = A z || bilinear discriminators
    k_phase3<<<SP_BLKS + BI_BLKS, 256>>>(
        row, col, vals, z_out, p_t,
        p_zaacc, p_zsacc, discW, discB, ret_out, reta_out);

    // 4. h = t@W2 and mean/disp from z0@W2 (tf32 tensor, shared W2 tile)
    k_wide<<<313 * 8, 256, WIDE_SMEM>>>(p_t, p_z0, W2,
                                        h_out, mean_out, disp_out);
}